// round 1
// baseline (speedup 1.0000x reference)
#include <cuda_runtime.h>
#include <math.h>

// Problem constants (fixed by the reference)
#define BB      32
#define SS      4096
#define HQN     32
#define HKVN    8
#define GG      4          // HQN / HKVN
#define DD      128
#define NSPLIT  16
#define CHUNK   (SS / NSPLIT)   // 256
#define SCALE_F 0.088388347648318447f   // 1/sqrt(128)
#define CAP_F   30.0f
#define NEGINF  -1e30f

// Split-KV scratch (no allocations allowed -> __device__ globals)
// pacc: [B][HKV][NSPLIT][G][D], pm/pl: [B][HKV][NSPLIT][G]
__device__ float g_pacc[(size_t)BB * HKVN * NSPLIT * GG * DD];
__device__ float g_pm[(size_t)BB * HKVN * NSPLIT * GG];
__device__ float g_pl[(size_t)BB * HKVN * NSPLIT * GG];

__global__ void __launch_bounds__(256)
attn_partial_kernel(const float* __restrict__ q,
                    const float* __restrict__ knew,
                    const float* __restrict__ vnew,
                    const float* __restrict__ kc,
                    const float* __restrict__ vc,
                    const int*   __restrict__ seq_lens)
{
    const int split = blockIdx.x;
    const int h     = blockIdx.y;
    const int b     = blockIdx.z;
    const int tid   = threadIdx.x;
    const int warp  = tid >> 5;
    const int lane  = tid & 31;

    __shared__ float q_sh[GG][DD];
    __shared__ float s_acc[8][GG][DD];
    __shared__ float s_m[8][GG];
    __shared__ float s_l[8][GG];

    // Load the 4 grouped query heads
    for (int i = tid; i < GG * DD; i += 256) {
        int g = i / DD, d = i % DD;
        q_sh[g][d] = q[(size_t)b * HQN * DD + (size_t)(h * GG + g) * DD + d];
    }
    __syncthreads();

    const int seq_len = seq_lens[b];
    const int start   = split * CHUNK;
    const int end     = min(start + CHUNK, seq_len);

    const int dcol = lane * 4;   // this lane owns columns [dcol, dcol+4)

    // Per-warp online-softmax state, per head
    float m[GG], l[GG], acc[GG][4];
#pragma unroll
    for (int g = 0; g < GG; g++) {
        m[g] = NEGINF; l[g] = 0.f;
#pragma unroll
        for (int j = 0; j < 4; j++) acc[g][j] = 0.f;
    }

    // q slice into registers
    float qreg[GG][4];
#pragma unroll
    for (int g = 0; g < GG; g++)
#pragma unroll
        for (int j = 0; j < 4; j++) qreg[g][j] = q_sh[g][dcol + j];

    const size_t bh_new = ((size_t)b * HKVN + h) * DD;

    for (int s = start + warp; s < end; s += 8) {
        const float* kptr;
        const float* vptr;
        if (s == seq_len - 1) {            // new-token substitution (cache write)
            kptr = knew + bh_new;
            vptr = vnew + bh_new;
        } else {
            size_t off = (((size_t)b * SS + s) * HKVN + h) * DD;
            kptr = kc + off;
            vptr = vc + off;
        }
        float4 k4 = *(const float4*)(kptr + dcol);
        float4 v4 = *(const float4*)(vptr + dcol);

        float dot[GG];
#pragma unroll
        for (int g = 0; g < GG; g++) {
            float t = qreg[g][0] * k4.x + qreg[g][1] * k4.y +
                      qreg[g][2] * k4.z + qreg[g][3] * k4.w;
#pragma unroll
            for (int o = 16; o > 0; o >>= 1)
                t += __shfl_xor_sync(0xffffffffu, t, o);
            dot[g] = t;
        }

#pragma unroll
        for (int g = 0; g < GG; g++) {
            float sc   = CAP_F * tanhf(dot[g] * (SCALE_F / CAP_F));
            float mn   = fmaxf(m[g], sc);
            float corr = __expf(m[g] - mn);
            float p    = __expf(sc - mn);
            l[g] = l[g] * corr + p;
            acc[g][0] = acc[g][0] * corr + p * v4.x;
            acc[g][1] = acc[g][1] * corr + p * v4.y;
            acc[g][2] = acc[g][2] * corr + p * v4.z;
            acc[g][3] = acc[g][3] * corr + p * v4.w;
            m[g] = mn;
        }
    }

    // Publish per-warp partials
#pragma unroll
    for (int g = 0; g < GG; g++) {
#pragma unroll
        for (int j = 0; j < 4; j++) s_acc[warp][g][dcol + j] = acc[g][j];
        if (lane == 0) { s_m[warp][g] = m[g]; s_l[warp][g] = l[g]; }
    }
    __syncthreads();

    // Combine 8 warps -> one split partial; 512 (g,d) items over 256 threads
    const size_t base = (((size_t)(b * HKVN + h) * NSPLIT) + split) * GG;
    for (int i = tid; i < GG * DD; i += 256) {
        int g = i / DD, d = i % DD;
        float M = NEGINF;
#pragma unroll
        for (int w = 0; w < 8; w++) M = fmaxf(M, s_m[w][g]);
        float a = 0.f, L = 0.f;
#pragma unroll
        for (int w = 0; w < 8; w++) {
            float e = __expf(s_m[w][g] - M);
            a += e * s_acc[w][g][d];
            L += e * s_l[w][g];
        }
        g_pacc[(base + g) * DD + d] = a;
        if (d == 0) { g_pm[base + g] = M; g_pl[base + g] = L; }
    }
}

__global__ void __launch_bounds__(128)
attn_reduce_kernel(float* __restrict__ out)
{
    // blockIdx.x in [0, B*HKV*G); threadIdx.x = d
    const int idx = blockIdx.x;
    const int g = idx % GG;
    const int h = (idx / GG) % HKVN;
    const int b = idx / (GG * HKVN);
    const int d = threadIdx.x;

    const size_t base = ((size_t)(b * HKVN + h) * NSPLIT) * GG + g;

    float mm[NSPLIT];
    float M = NEGINF;
#pragma unroll
    for (int i = 0; i < NSPLIT; i++) {
        mm[i] = g_pm[base + (size_t)i * GG];
        M = fmaxf(M, mm[i]);
    }
    float denom = 0.f, a = 0.f;
#pragma unroll
    for (int i = 0; i < NSPLIT; i++) {
        float e = __expf(mm[i] - M);
        denom += e * g_pl[base + (size_t)i * GG];
        a     += e * g_pacc[(base + (size_t)i * GG) * DD + d];
    }
    out[(size_t)b * HQN * DD + (size_t)(h * GG + g) * DD + d] = a / denom;
}

extern "C" void kernel_launch(void* const* d_in, const int* in_sizes, int n_in,
                              void* d_out, int out_size)
{
    const float* q    = (const float*)d_in[0];
    const float* knew = (const float*)d_in[1];
    const float* vnew = (const float*)d_in[2];
    const float* kc   = (const float*)d_in[3];
    const float* vc   = (const float*)d_in[4];
    const int*   sl   = (const int*)  d_in[5];
    float* out = (float*)d_out;

    dim3 grid(NSPLIT, HKVN, BB);
    attn_partial_kernel<<<grid, 256>>>(q, knew, vnew, kc, vc, sl);
    attn_reduce_kernel<<<BB * HKVN * GG, 128>>>(out);
}

// round 2
// speedup vs baseline: 1.4485x; 1.4485x over previous
#include <cuda_runtime.h>
#include <math.h>

// Problem constants (fixed by the reference)
#define BB      32
#define SS      4096
#define HQN     32
#define HKVN    8
#define GG      4          // HQN / HKVN
#define DD      128
#define NSPLIT  16
#define CHUNK   (SS / NSPLIT)   // 256
#define KVROW   (HKVN * DD)     // 1024 floats between consecutive s rows
#define SCALE_F 0.088388347648318447f   // 1/sqrt(128)
// p = exp(sc - 30) where sc = 30*tanh(dot*SCALE/30)
//   = exp(-60 / (exp(dot*SCALE/15) + 1))
#define C2_F    (SCALE_F / 15.0f)

// Split-KV scratch (no allocations -> __device__ globals)
// pacc: [B][HKV][NSPLIT][G][D], pl: [B][HKV][NSPLIT][G]   (fixed m = 30, so no pm)
__device__ float g_pacc[(size_t)BB * HKVN * NSPLIT * GG * DD];
__device__ float g_pl[(size_t)BB * HKVN * NSPLIT * GG];

typedef unsigned long long u64;

__device__ __forceinline__ void fma2(u64 &d, u64 a, u64 b) {
    asm("fma.rn.f32x2 %0, %1, %2, %0;" : "+l"(d) : "l"(a), "l"(b));
}
__device__ __forceinline__ u64 pk(float x, float y) {
    u64 r; asm("mov.b64 %0, {%1, %2};" : "=l"(r) : "f"(x), "f"(y)); return r;
}
__device__ __forceinline__ float usum(u64 v) {
    float lo, hi; asm("mov.b64 {%0, %1}, %2;" : "=f"(lo), "=f"(hi) : "l"(v));
    return lo + hi;
}

// Per-warp state: lane = (half, lh); lh owns 8 d-columns [lh*8, lh*8+8)
struct WState {
    u64 q2[GG][4];    // packed q pairs for this lane's 8 columns, per head
    u64 acc[GG][4];   // packed output accumulators
    float l[GG];
};

// Process one s position per half-warp.
// kx/vx: two 16B chunks each (this lane's 8 floats of the K/V row). ok: validity.
__device__ __forceinline__ void body(WState &st, ulonglong2 kx0, ulonglong2 kx1,
                                     ulonglong2 vx0, ulonglong2 vx1, bool ok)
{
    float d[GG];
#pragma unroll
    for (int g = 0; g < GG; g++) {
        u64 t = pk(0.f, 0.f);
        fma2(t, st.q2[g][0], kx0.x);
        fma2(t, st.q2[g][1], kx0.y);
        fma2(t, st.q2[g][2], kx1.x);
        fma2(t, st.q2[g][3], kx1.y);
        d[g] = usum(t);
    }
    // reduce over the 16 lanes of this half (xor offsets stay within the half)
#pragma unroll
    for (int off = 8; off > 0; off >>= 1) {
#pragma unroll
        for (int g = 0; g < GG; g++)
            d[g] += __shfl_xor_sync(0xffffffffu, d[g], off);
    }
#pragma unroll
    for (int g = 0; g < GG; g++) {
        float t = __expf(d[g] * C2_F);
        float p = ok ? __expf(-60.0f * __frcp_rn(t + 1.0f)) : 0.0f;
        // __frcp_rn is IEEE (slow); use fast reciprocal instead:
        // (computed below with fast path)
        p = ok ? __expf(__fdividef(-60.0f, t + 1.0f)) : 0.0f;
        st.l[g] += p;
        u64 pp = pk(p, p);
        fma2(st.acc[g][0], pp, vx0.x);
        fma2(st.acc[g][1], pp, vx0.y);
        fma2(st.acc[g][2], pp, vx1.x);
        fma2(st.acc[g][3], pp, vx1.y);
    }
}

__global__ void __launch_bounds__(128)
attn_partial_kernel(const float* __restrict__ q,
                    const float* __restrict__ knew,
                    const float* __restrict__ vnew,
                    const float* __restrict__ kc,
                    const float* __restrict__ vc,
                    const int*   __restrict__ seq_lens)
{
    const int split = blockIdx.x;
    const int h     = blockIdx.y;
    const int b     = blockIdx.z;
    const int tid   = threadIdx.x;
    const int w     = tid >> 5;          // 4 warps
    const int lane  = tid & 31;
    const int half  = lane >> 4;         // 0 or 1 -> which s of the pair
    const int lh    = lane & 15;
    const int dcol  = lh * 8;            // this lane's 8 d-columns

    __shared__ float s_acc[4][GG][DD];
    __shared__ float s_l[4][GG];

    const int seq_len = seq_lens[b];
    const int start   = split * CHUNK;
    const size_t pbase = (((size_t)(b * HKVN + h) * NSPLIT) + split) * GG;

    if (start >= seq_len) {
        // empty split: publish zeros (scratch is persistent across replays)
        for (int i = tid; i < GG * DD; i += 128)
            g_pacc[pbase * DD + i] = 0.f;
        if (tid < GG) g_pl[pbase + tid] = 0.f;
        return;
    }

    WState st;
    {
        const float* qb = q + (size_t)b * HQN * DD + (size_t)h * GG * DD + dcol;
#pragma unroll
        for (int g = 0; g < GG; g++) {
            float4 qa = *(const float4*)(qb + (size_t)g * DD);
            float4 qc = *(const float4*)(qb + (size_t)g * DD + 4);
            st.q2[g][0] = pk(qa.x, qa.y);
            st.q2[g][1] = pk(qa.z, qa.w);
            st.q2[g][2] = pk(qc.x, qc.y);
            st.q2[g][3] = pk(qc.z, qc.w);
            st.acc[g][0] = st.acc[g][1] = st.acc[g][2] = st.acc[g][3] = pk(0.f, 0.f);
            st.l[g] = 0.f;
        }
    }

    // cache rows: s in [start, end_c); s = seq_len-1 comes from knew/vnew instead
    const int end_c = min(start + CHUNK, seq_len - 1);
    const float* kb = kc + ((size_t)b * SS) * KVROW + (size_t)h * DD + dcol;
    const float* vb = vc + ((size_t)b * SS) * KVROW + (size_t)h * DD + dcol;

    for (int sb = start + w * 4; sb < end_c; sb += 16) {
        const int sA = sb + half;
        const int sB = sb + 2 + half;
        const bool okA = sA < end_c;
        const bool okB = sB < end_c;
        const size_t rA = (size_t)(okA ? sA : end_c - 1) * KVROW;
        const size_t rB = (size_t)(okB ? sB : end_c - 1) * KVROW;
        // 8 LDG.128 issued up front for MLP
        ulonglong2 kA0 = *(const ulonglong2*)(kb + rA);
        ulonglong2 kA1 = *(const ulonglong2*)(kb + rA + 4);
        ulonglong2 vA0 = *(const ulonglong2*)(vb + rA);
        ulonglong2 vA1 = *(const ulonglong2*)(vb + rA + 4);
        ulonglong2 kB0 = *(const ulonglong2*)(kb + rB);
        ulonglong2 kB1 = *(const ulonglong2*)(kb + rB + 4);
        ulonglong2 vB0 = *(const ulonglong2*)(vb + rB);
        ulonglong2 vB1 = *(const ulonglong2*)(vb + rB + 4);
        body(st, kA0, kA1, vA0, vA1, okA);
        body(st, kB0, kB1, vB0, vB1, okB);
    }

    // new token (s = seq_len-1) handled once, by warp 0, half 0
    const int last = seq_len - 1;
    if (w == 0 && last >= start && last < start + CHUNK) {
        const float* kp = knew + ((size_t)b * HKVN + h) * DD + dcol;
        const float* vp = vnew + ((size_t)b * HKVN + h) * DD + dcol;
        ulonglong2 k0 = *(const ulonglong2*)(kp);
        ulonglong2 k1 = *(const ulonglong2*)(kp + 4);
        ulonglong2 v0 = *(const ulonglong2*)(vp);
        ulonglong2 v1 = *(const ulonglong2*)(vp + 4);
        body(st, k0, k1, v0, v1, half == 0);
    }

    // fold the two halves together (same dcol in both halves)
#pragma unroll
    for (int g = 0; g < GG; g++) {
#pragma unroll
        for (int j = 0; j < 4; j++) {
            u64 o = __shfl_xor_sync(0xffffffffu, st.acc[g][j], 16);
            float2 a = *(float2*)&st.acc[g][j];
            float2 ob = *(float2*)&o;
            a.x += ob.x; a.y += ob.y;
            st.acc[g][j] = pk(a.x, a.y);
        }
        st.l[g] += __shfl_xor_sync(0xffffffffu, st.l[g], 16);
    }

    // publish per-warp partials (lanes 0-15 hold the totals)
    if (half == 0) {
#pragma unroll
        for (int g = 0; g < GG; g++) {
            u64* dst = (u64*)&s_acc[w][g][dcol];
#pragma unroll
            for (int j = 0; j < 4; j++) dst[j] = st.acc[g][j];
            if (lh == 0) s_l[w][g] = st.l[g];
        }
    }
    __syncthreads();

    // combine 4 warps -> split partial (plain sums; fixed m)
    for (int i = tid; i < GG * DD; i += 128) {
        int g = i >> 7, d = i & 127;
        float a = s_acc[0][g][d] + s_acc[1][g][d] + s_acc[2][g][d] + s_acc[3][g][d];
        g_pacc[(pbase + g) * DD + d] = a;
    }
    if (tid < GG) {
        float L = s_l[0][tid] + s_l[1][tid] + s_l[2][tid] + s_l[3][tid];
        g_pl[pbase + tid] = L;
    }
}

__global__ void __launch_bounds__(128)
attn_reduce_kernel(float* __restrict__ out)
{
    // blockIdx.x in [0, B*HKV*G); threadIdx.x = d
    const int idx = blockIdx.x;
    const int g = idx % GG;
    const int h = (idx / GG) % HKVN;
    const int b = idx / (GG * HKVN);
    const int d = threadIdx.x;

    const size_t base = ((size_t)(b * HKVN + h) * NSPLIT) * GG + g;

    float denom = 0.f, a = 0.f;
#pragma unroll
    for (int i = 0; i < NSPLIT; i++) {
        denom += g_pl[base + (size_t)i * GG];
        a     += g_pacc[(base + (size_t)i * GG) * DD + d];
    }
    out[(size_t)b * HQN * DD + (size_t)(h * GG + g) * DD + d] = a / denom;
}

extern "C" void kernel_launch(void* const* d_in, const int* in_sizes, int n_in,
                              void* d_out, int out_size)
{
    const float* q    = (const float*)d_in[0];
    const float* knew = (const float*)d_in[1];
    const float* vnew = (const float*)d_in[2];
    const float* kc   = (const float*)d_in[3];
    const float* vc   = (const float*)d_in[4];
    const int*   sl   = (const int*)  d_in[5];
    float* out = (float*)d_out;

    dim3 grid(NSPLIT, HKVN, BB);
    attn_partial_kernel<<<grid, 128>>>(q, knew, vnew, kc, vc, sl);
    attn_reduce_kernel<<<BB * HKVN * GG, 128>>>(out);
}

// round 3
// speedup vs baseline: 1.5569x; 1.0748x over previous
#include <cuda_runtime.h>
#include <math.h>

// Problem constants (fixed by the reference)
#define BB      32
#define SS      4096
#define HQN     32
#define HKVN    8
#define GG      4          // HQN / HKVN
#define DD      128
#define NSPLIT  16
#define CHUNK   (SS / NSPLIT)   // 256
#define KVROW   (HKVN * DD)     // 1024 floats between consecutive s rows
#define SCALE_F 0.088388347648318447f   // 1/sqrt(128)
// p = exp(sc - 30), sc = 30*tanh(dot*SCALE/30)  =>  p = exp(-60/(exp(dot*SCALE/15)+1))
#define C2_F    (SCALE_F / 15.0f)

// Split-KV scratch (no allocations -> __device__ globals)
__device__ float g_pacc[(size_t)BB * HKVN * NSPLIT * GG * DD];
__device__ float g_pl[(size_t)BB * HKVN * NSPLIT * GG];

typedef unsigned long long u64;

__device__ __forceinline__ void fma2(u64 &d, u64 a, u64 b) {
    asm("fma.rn.f32x2 %0, %1, %2, %0;" : "+l"(d) : "l"(a), "l"(b));
}
__device__ __forceinline__ u64 pk(float x, float y) {
    u64 r; asm("mov.b64 %0, {%1, %2};" : "=l"(r) : "f"(x), "f"(y)); return r;
}
__device__ __forceinline__ float usum(u64 v) {
    float lo, hi; asm("mov.b64 {%0, %1}, %2;" : "=f"(lo), "=f"(hi) : "l"(v));
    return lo + hi;
}

struct Buf {               // one (2-s) stage of the pipeline: this lane's 8 floats of K and V
    u64 k[4];
    u64 v[4];
    bool ok;
};

__device__ __forceinline__ Buf load_buf(const float* __restrict__ kb,
                                        const float* __restrict__ vb,
                                        int s, int end_c)
{
    Buf r;
    r.ok = (s < end_c);
    size_t row = (size_t)(r.ok ? s : (end_c - 1)) * KVROW;
    float4 ka = __ldcs((const float4*)(kb + row));
    float4 kc4 = __ldcs((const float4*)(kb + row + 4));
    float4 va = __ldcs((const float4*)(vb + row));
    float4 vc4 = __ldcs((const float4*)(vb + row + 4));
    r.k[0] = pk(ka.x, ka.y);  r.k[1] = pk(ka.z, ka.w);
    r.k[2] = pk(kc4.x, kc4.y); r.k[3] = pk(kc4.z, kc4.w);
    r.v[0] = pk(va.x, va.y);  r.v[1] = pk(va.z, va.w);
    r.v[2] = pk(vc4.x, vc4.y); r.v[3] = pk(vc4.z, vc4.w);
    return r;
}

struct WState {
    u64 q2[GG][4];    // packed q pairs for this lane's 8 columns, per head
    u64 acc[GG][4];   // packed output accumulators
    float l[GG];
};

// Process one s position per half-warp (2 s per warp per call).
__device__ __forceinline__ void body(WState &st, const Buf &bf)
{
    float d[GG];
#pragma unroll
    for (int g = 0; g < GG; g++) {
        u64 t = pk(0.f, 0.f);
        fma2(t, st.q2[g][0], bf.k[0]);
        fma2(t, st.q2[g][1], bf.k[1]);
        fma2(t, st.q2[g][2], bf.k[2]);
        fma2(t, st.q2[g][3], bf.k[3]);
        d[g] = usum(t);
    }
    // reduce over the 16 lanes of this half (xor offsets stay within the half)
#pragma unroll
    for (int off = 8; off > 0; off >>= 1) {
#pragma unroll
        for (int g = 0; g < GG; g++)
            d[g] += __shfl_xor_sync(0xffffffffu, d[g], off);
    }
#pragma unroll
    for (int g = 0; g < GG; g++) {
        float t = __expf(d[g] * C2_F);
        float p = __expf(__fdividef(-60.0f, t + 1.0f));
        p = bf.ok ? p : 0.0f;
        st.l[g] += p;
        u64 pp = pk(p, p);
        fma2(st.acc[g][0], pp, bf.v[0]);
        fma2(st.acc[g][1], pp, bf.v[1]);
        fma2(st.acc[g][2], pp, bf.v[2]);
        fma2(st.acc[g][3], pp, bf.v[3]);
    }
}

__global__ void __launch_bounds__(128, 4)
attn_partial_kernel(const float* __restrict__ q,
                    const float* __restrict__ knew,
                    const float* __restrict__ vnew,
                    const float* __restrict__ kc,
                    const float* __restrict__ vc,
                    const int*   __restrict__ seq_lens)
{
    const int split = blockIdx.x;
    const int h     = blockIdx.y;
    const int b     = blockIdx.z;
    const int tid   = threadIdx.x;
    const int w     = tid >> 5;          // 4 warps
    const int lane  = tid & 31;
    const int half  = lane >> 4;         // which s of the warp's pair
    const int lh    = lane & 15;
    const int dcol  = lh * 8;            // this lane's 8 d-columns

    __shared__ float s_acc[4][GG][DD];
    __shared__ float s_l[4][GG];

    const int seq_len = seq_lens[b];
    const int start   = split * CHUNK;
    const size_t pbase = (((size_t)(b * HKVN + h) * NSPLIT) + split) * GG;

    if (start >= seq_len) {
        for (int i = tid; i < GG * DD; i += 128)
            g_pacc[pbase * DD + i] = 0.f;
        if (tid < GG) g_pl[pbase + tid] = 0.f;
        return;
    }

    WState st;
    {
        const float* qb = q + (size_t)b * HQN * DD + (size_t)h * GG * DD + dcol;
#pragma unroll
        for (int g = 0; g < GG; g++) {
            float4 qa = *(const float4*)(qb + (size_t)g * DD);
            float4 qc = *(const float4*)(qb + (size_t)g * DD + 4);
            st.q2[g][0] = pk(qa.x, qa.y);
            st.q2[g][1] = pk(qa.z, qa.w);
            st.q2[g][2] = pk(qc.x, qc.y);
            st.q2[g][3] = pk(qc.z, qc.w);
            st.acc[g][0] = st.acc[g][1] = st.acc[g][2] = st.acc[g][3] = pk(0.f, 0.f);
            st.l[g] = 0.f;
        }
    }

    // cache rows: s in [start, end_c); s = seq_len-1 comes from knew/vnew instead
    const int end_c = min(start + CHUNK, seq_len - 1);
    const float* kb = kc + ((size_t)b * SS) * KVROW + (size_t)h * DD + dcol;
    const float* vb = vc + ((size_t)b * SS) * KVROW + (size_t)h * DD + dcol;

    // uniform trip count across all warps: each iteration covers 8 s (4 warps x 2 s)
    const int span = end_c - start;                 // may be <= 0
    const int n_it = (span > 0) ? ((span + 7) >> 3) : 0;
    const int s0   = start + w * 2 + half;          // this lane's first s

    if (n_it > 0) {
        // ---- software pipeline, depth 2: prefetch iter i+1 before processing iter i
        Buf cur = load_buf(kb, vb, s0, end_c);
        for (int it = 1; it < n_it; it++) {
            Buf nxt = load_buf(kb, vb, s0 + it * 8, end_c);
            body(st, cur);
            cur = nxt;
        }
        body(st, cur);
    }

    // new token (s = seq_len-1) handled once, by warp 0, half 0
    const int last = seq_len - 1;
    if (w == 0 && last >= start && last < start + CHUNK) {
        const float* kp = knew + ((size_t)b * HKVN + h) * DD + dcol;
        const float* vp = vnew + ((size_t)b * HKVN + h) * DD + dcol;
        Buf nb;
        nb.ok = (half == 0);
        float4 ka = *(const float4*)(kp);
        float4 kc4 = *(const float4*)(kp + 4);
        float4 va = *(const float4*)(vp);
        float4 vc4 = *(const float4*)(vp + 4);
        nb.k[0] = pk(ka.x, ka.y);  nb.k[1] = pk(ka.z, ka.w);
        nb.k[2] = pk(kc4.x, kc4.y); nb.k[3] = pk(kc4.z, kc4.w);
        nb.v[0] = pk(va.x, va.y);  nb.v[1] = pk(va.z, va.w);
        nb.v[2] = pk(vc4.x, vc4.y); nb.v[3] = pk(vc4.z, vc4.w);
        body(st, nb);
    }

    // fold the two halves together (same dcol in both halves)
#pragma unroll
    for (int g = 0; g < GG; g++) {
#pragma unroll
        for (int j = 0; j < 4; j++) {
            u64 o = __shfl_xor_sync(0xffffffffu, st.acc[g][j], 16);
            float2 a = *(float2*)&st.acc[g][j];
            float2 ob = *(float2*)&o;
            a.x += ob.x; a.y += ob.y;
            st.acc[g][j] = pk(a.x, a.y);
        }
        st.l[g] += __shfl_xor_sync(0xffffffffu, st.l[g], 16);
    }

    // publish per-warp partials (lanes 0-15 hold the totals)
    if (half == 0) {
#pragma unroll
        for (int g = 0; g < GG; g++) {
            u64* dst = (u64*)&s_acc[w][g][dcol];
#pragma unroll
            for (int j = 0; j < 4; j++) dst[j] = st.acc[g][j];
            if (lh == 0) s_l[w][g] = st.l[g];
        }
    }
    __syncthreads();

    // combine 4 warps -> split partial (plain sums; fixed softmax shift m=30)
    for (int i = tid; i < GG * DD; i += 128) {
        int g = i >> 7, d = i & 127;
        float a = s_acc[0][g][d] + s_acc[1][g][d] + s_acc[2][g][d] + s_acc[3][g][d];
        g_pacc[(pbase + g) * DD + d] = a;
    }
    if (tid < GG) {
        float L = s_l[0][tid] + s_l[1][tid] + s_l[2][tid] + s_l[3][tid];
        g_pl[pbase + tid] = L;
    }
}

__global__ void __launch_bounds__(128)
attn_reduce_kernel(float* __restrict__ out)
{
    const int idx = blockIdx.x;
    const int g = idx % GG;
    const int h = (idx / GG) % HKVN;
    const int b = idx / (GG * HKVN);
    const int d = threadIdx.x;

    const size_t base = ((size_t)(b * HKVN + h) * NSPLIT) * GG + g;

    float denom = 0.f, a = 0.f;
#pragma unroll
    for (int i = 0; i < NSPLIT; i++) {
        denom += g_pl[base + (size_t)i * GG];
        a     += g_pacc[(base + (size_t)i * GG) * DD + d];
    }
    out[(size_t)b * HQN * DD + (size_t)(h * GG + g) * DD + d] = a / denom;
}

extern "C" void kernel_launch(void* const* d_in, const int* in_sizes, int n_in,
                              void* d_out, int out_size)
{
    const float* q    = (const float*)d_in[0];
    const float* knew = (const float*)d_in[1];
    const float* vnew = (const float*)d_in[2];
    const float* kc   = (const float*)d_in[3];
    const float* vc   = (const float*)d_in[4];
    const int*   sl   = (const int*)  d_in[5];
    float* out = (float*)d_out;

    dim3 grid(NSPLIT, HKVN, BB);
    attn_partial_kernel<<<grid, 128>>>(q, knew, vnew, kc, vc, sl);
    attn_reduce_kernel<<<BB * HKVN * GG, 128>>>(out);
}

// round 4
// speedup vs baseline: 1.6187x; 1.0397x over previous
#include <cuda_runtime.h>
#include <math.h>

// Problem constants (fixed by the reference)
#define BB      32
#define SS      4096
#define HQN     32
#define HKVN    8
#define GG      4          // HQN / HKVN
#define DD      128
#define NSPLIT  32
#define CHUNK   (SS / NSPLIT)   // 128
#define KVROW   (HKVN * DD)     // 1024 floats between consecutive s rows
#define SCALE_F 0.088388347648318447f   // 1/sqrt(128)
// p = exp(sc - 30), sc = 30*tanh(dot*SCALE/30)  =>  p = exp(-60/(exp(dot*SCALE/15)+1))
#define C2_F    (SCALE_F / 15.0f)

// Split-KV scratch (no allocations -> __device__ globals)
// pacc: [B][HKV][NSPLIT][G][D], pl: [B][HKV][NSPLIT][G]
__device__ float g_pacc[(size_t)BB * HKVN * NSPLIT * GG * DD];
__device__ float g_pl[(size_t)BB * HKVN * NSPLIT * GG];

typedef unsigned long long u64;

__device__ __forceinline__ void fma2(u64 &d, u64 a, u64 b) {
    asm("fma.rn.f32x2 %0, %1, %2, %0;" : "+l"(d) : "l"(a), "l"(b));
}
__device__ __forceinline__ u64 pk(float x, float y) {
    u64 r; asm("mov.b64 %0, {%1, %2};" : "=l"(r) : "f"(x), "f"(y)); return r;
}
__device__ __forceinline__ float usum(u64 v) {
    float lo, hi; asm("mov.b64 {%0, %1}, %2;" : "=f"(lo), "=f"(hi) : "l"(v));
    return lo + hi;
}

struct Buf {               // one pipeline stage: this lane's 8 floats of K and V
    u64 k[4];
    u64 v[4];
    bool ok;
};

__device__ __forceinline__ Buf load_buf(const float* __restrict__ kb,
                                        const float* __restrict__ vb,
                                        int s, int end_c)
{
    Buf r;
    r.ok = (s < end_c);
    size_t row = (size_t)(r.ok ? s : (end_c - 1)) * KVROW;
    float4 ka  = __ldcs((const float4*)(kb + row));
    float4 kc4 = __ldcs((const float4*)(kb + row + 4));
    float4 va  = __ldcs((const float4*)(vb + row));
    float4 vc4 = __ldcs((const float4*)(vb + row + 4));
    r.k[0] = pk(ka.x, ka.y);   r.k[1] = pk(ka.z, ka.w);
    r.k[2] = pk(kc4.x, kc4.y); r.k[3] = pk(kc4.z, kc4.w);
    r.v[0] = pk(va.x, va.y);   r.v[1] = pk(va.z, va.w);
    r.v[2] = pk(vc4.x, vc4.y); r.v[3] = pk(vc4.z, vc4.w);
    return r;
}

struct WState {
    u64 q2[GG][4];    // packed q pairs for this lane's 8 columns, per head
    u64 acc[GG][4];   // packed output accumulators
    float l[GG];
};

// Process one s position per half-warp (2 s per warp per call).
__device__ __forceinline__ void body(WState &st, const Buf &bf)
{
    float d[GG];
#pragma unroll
    for (int g = 0; g < GG; g++) {
        u64 t = pk(0.f, 0.f);
        fma2(t, st.q2[g][0], bf.k[0]);
        fma2(t, st.q2[g][1], bf.k[1]);
        fma2(t, st.q2[g][2], bf.k[2]);
        fma2(t, st.q2[g][3], bf.k[3]);
        d[g] = usum(t);
    }
#pragma unroll
    for (int off = 8; off > 0; off >>= 1) {
#pragma unroll
        for (int g = 0; g < GG; g++)
            d[g] += __shfl_xor_sync(0xffffffffu, d[g], off);
    }
#pragma unroll
    for (int g = 0; g < GG; g++) {
        float t = __expf(d[g] * C2_F);
        float p = __expf(__fdividef(-60.0f, t + 1.0f));
        p = bf.ok ? p : 0.0f;
        st.l[g] += p;
        u64 pp = pk(p, p);
        fma2(st.acc[g][0], pp, bf.v[0]);
        fma2(st.acc[g][1], pp, bf.v[1]);
        fma2(st.acc[g][2], pp, bf.v[2]);
        fma2(st.acc[g][3], pp, bf.v[3]);
    }
}

__global__ void __launch_bounds__(128, 4)
attn_partial_kernel(const float* __restrict__ q,
                    const float* __restrict__ knew,
                    const float* __restrict__ vnew,
                    const float* __restrict__ kc,
                    const float* __restrict__ vc,
                    const int*   __restrict__ seq_lens)
{
    const int split = blockIdx.x;
    const int h     = blockIdx.y;
    const int b     = blockIdx.z;
    const int tid   = threadIdx.x;
    const int w     = tid >> 5;          // 4 warps
    const int lane  = tid & 31;
    const int half  = lane >> 4;
    const int lh    = lane & 15;
    const int dcol  = lh * 8;

    const int seq_len = seq_lens[b];
    const int start   = split * CHUNK;

    // invalid split: nothing to do, reduce kernel never reads this slot
    if (start >= seq_len) return;

    __shared__ float s_acc[4][GG][DD];
    __shared__ float s_l[4][GG];

    const size_t pbase = (((size_t)(b * HKVN + h) * NSPLIT) + split) * GG;

    WState st;
    {
        const float* qb = q + (size_t)b * HQN * DD + (size_t)h * GG * DD + dcol;
#pragma unroll
        for (int g = 0; g < GG; g++) {
            float4 qa = *(const float4*)(qb + (size_t)g * DD);
            float4 qc = *(const float4*)(qb + (size_t)g * DD + 4);
            st.q2[g][0] = pk(qa.x, qa.y);
            st.q2[g][1] = pk(qa.z, qa.w);
            st.q2[g][2] = pk(qc.x, qc.y);
            st.q2[g][3] = pk(qc.z, qc.w);
            st.acc[g][0] = st.acc[g][1] = st.acc[g][2] = st.acc[g][3] = pk(0.f, 0.f);
            st.l[g] = 0.f;
        }
    }

    // cache rows: s in [start, end_c); s = seq_len-1 comes from knew/vnew instead
    const int end_c = min(start + CHUNK, seq_len - 1);
    const float* kb = kc + ((size_t)b * SS) * KVROW + (size_t)h * DD + dcol;
    const float* vb = vc + ((size_t)b * SS) * KVROW + (size_t)h * DD + dcol;

    const int span = end_c - start;                 // may be <= 0
    const int n_it = (span > 0) ? ((span + 7) >> 3) : 0;
    const int s0   = start + w * 2 + half;

    if (n_it > 0) {
        // depth-2 software pipeline: prefetch iter i+1 before processing iter i
        Buf cur = load_buf(kb, vb, s0, end_c);
        for (int it = 1; it < n_it; it++) {
            Buf nxt = load_buf(kb, vb, s0 + it * 8, end_c);
            body(st, cur);
            cur = nxt;
        }
        body(st, cur);
    }

    // new token (s = seq_len-1), handled once by warp 0 / half 0
    const int last = seq_len - 1;
    if (w == 0 && last >= start && last < start + CHUNK) {
        const float* kp = knew + ((size_t)b * HKVN + h) * DD + dcol;
        const float* vp = vnew + ((size_t)b * HKVN + h) * DD + dcol;
        Buf nb;
        nb.ok = (half == 0);
        float4 ka  = *(const float4*)(kp);
        float4 kc4 = *(const float4*)(kp + 4);
        float4 va  = *(const float4*)(vp);
        float4 vc4 = *(const float4*)(vp + 4);
        nb.k[0] = pk(ka.x, ka.y);   nb.k[1] = pk(ka.z, ka.w);
        nb.k[2] = pk(kc4.x, kc4.y); nb.k[3] = pk(kc4.z, kc4.w);
        nb.v[0] = pk(va.x, va.y);   nb.v[1] = pk(va.z, va.w);
        nb.v[2] = pk(vc4.x, vc4.y); nb.v[3] = pk(vc4.z, vc4.w);
        body(st, nb);
    }

    // fold halves
#pragma unroll
    for (int g = 0; g < GG; g++) {
#pragma unroll
        for (int j = 0; j < 4; j++) {
            u64 o = __shfl_xor_sync(0xffffffffu, st.acc[g][j], 16);
            float2 a = *(float2*)&st.acc[g][j];
            float2 ob = *(float2*)&o;
            a.x += ob.x; a.y += ob.y;
            st.acc[g][j] = pk(a.x, a.y);
        }
        st.l[g] += __shfl_xor_sync(0xffffffffu, st.l[g], 16);
    }

    if (half == 0) {
#pragma unroll
        for (int g = 0; g < GG; g++) {
            u64* dst = (u64*)&s_acc[w][g][dcol];
#pragma unroll
            for (int j = 0; j < 4; j++) dst[j] = st.acc[g][j];
            if (lh == 0) s_l[w][g] = st.l[g];
        }
    }
    __syncthreads();

    // combine 4 warps -> split partial (plain sums; fixed softmax shift m=30)
    for (int i = tid; i < GG * DD; i += 128) {
        int g = i >> 7, d = i & 127;
        float a = s_acc[0][g][d] + s_acc[1][g][d] + s_acc[2][g][d] + s_acc[3][g][d];
        g_pacc[(pbase + g) * DD + d] = a;
    }
    if (tid < GG) {
        float L = s_l[0][tid] + s_l[1][tid] + s_l[2][tid] + s_l[3][tid];
        g_pl[pbase + tid] = L;
    }
}

__global__ void __launch_bounds__(128)
attn_reduce_kernel(float* __restrict__ out, const int* __restrict__ seq_lens)
{
    const int idx = blockIdx.x;
    const int g = idx % GG;
    const int h = (idx / GG) % HKVN;
    const int b = idx / (GG * HKVN);
    const int d = threadIdx.x;

    const int seq_len = seq_lens[b];
    const int n_valid = min(NSPLIT, (seq_len + CHUNK - 1) / CHUNK);

    const size_t base = ((size_t)(b * HKVN + h) * NSPLIT) * GG + g;

    float denom = 0.f, a = 0.f;
    for (int i = 0; i < n_valid; i++) {
        denom += g_pl[base + (size_t)i * GG];
        a     += g_pacc[(base + (size_t)i * GG) * DD + d];
    }
    out[(size_t)b * HQN * DD + (size_t)(h * GG + g) * DD + d] = a / denom;
}

extern "C" void kernel_launch(void* const* d_in, const int* in_sizes, int n_in,
                              void* d_out, int out_size)
{
    const float* q    = (const float*)d_in[0];
    const float* knew = (const float*)d_in[1];
    const float* vnew = (const float*)d_in[2];
    const float* kc   = (const float*)d_in[3];
    const float* vc   = (const float*)d_in[4];
    const int*   sl   = (const int*)  d_in[5];
    float* out = (float*)d_out;

    dim3 grid(NSPLIT, HKVN, BB);
    attn_partial_kernel<<<grid, 128>>>(q, knew, vnew, kc, vc, sl);
    attn_reduce_kernel<<<BB * HKVN * GG, 128>>>(out, sl);
}